// round 12
// baseline (speedup 1.0000x reference)
#include <cuda_runtime.h>
#include <math.h>

typedef unsigned long long u64;

// Transposed weights in global scratch: WT_G[i*128 + o*4 + k]
__device__ __align__(128) float WT_G[32 * 32 * 4];

__global__ void transpose_W_kernel(const float* __restrict__ lin_W) {
    const int s = blockIdx.x * 128 + threadIdx.x;   // 0..4095
    const int o = s >> 7, i = (s >> 2) & 31, k = s & 3;
    WT_G[i * 128 + o * 4 + k] = lin_W[s];
}

// ---- packed f32x2 helpers ----
__device__ __forceinline__ u64 pack2(float lo, float hi) {
    u64 r; asm("mov.b64 %0, {%1, %2};" : "=l"(r) : "f"(lo), "f"(hi)); return r;
}
__device__ __forceinline__ float low2(u64 v) {
    float lo, hi; asm("mov.b64 {%0, %1}, %2;" : "=f"(lo), "=f"(hi) : "l"(v)); return lo;
}
__device__ __forceinline__ void fma2(u64& d, u64 a, u64 b) {
    asm("fma.rn.f32x2 %0, %1, %2, %0;" : "+l"(d) : "l"(a), "l"(b));
}

// rotor_exp of bivector -> components {scalar, e12, e13, e23}
__device__ __forceinline__ void rotor_exp4(float b0, float b1, float b2, float r[4]) {
    float t2 = fmaf(b0, b0, fmaf(b1, b1, b2 * b2));
    float th = sqrtf(t2);
    float sn, cs;
    sincosf(th, &sn, &cs);
    float sinc = (th > 1e-6f) ? sn / fmaxf(th, 1e-6f) : 1.0f;
    r[0] = cs; r[1] = sinc * b0; r[2] = sinc * b1; r[3] = sinc * b2;
}

// 3x3 rotation matrix from unit rotor u = (scalar, e12, e13, e23).
__device__ __forceinline__ void rotor_to_mat(const float u[4], float m[9]) {
    const float qw = u[0], qx = -u[3], qy = u[2], qz = -u[1];
    const float x2 = qx + qx, y2 = qy + qy, z2 = qz + qz;
    const float xx = qx * x2, yy = qy * y2, zz = qz * z2;
    const float xy = qx * y2, xz = qx * z2, yz = qy * z2;
    const float wx = qw * x2, wy = qw * y2, wz = qw * z2;
    m[0] = 1.f - (yy + zz); m[1] = xy - wz;        m[2] = xz + wy;
    m[3] = xy + wz;         m[4] = 1.f - (xx + zz); m[5] = yz - wx;
    m[6] = xz - wy;         m[7] = yz + wx;        m[8] = 1.f - (xx + yy);
}

__device__ __forceinline__ void mat_apply(const float4 A0, const float4 A1, const float A2,
                                          float v1, float v2, float v3,
                                          float& o1, float& o2, float& o3) {
    o1 = fmaf(A0.x, v1, fmaf(A0.y, v2, A0.z * v3));
    o2 = fmaf(A0.w, v1, fmaf(A1.x, v2, A1.y * v3));
    o3 = fmaf(A1.z, v1, fmaf(A1.w, v2, A2  * v3));
}

#define NCH  32
#define WPB  4            // warps per block (128 threads)
#define BPW  8            // batch rows per warp (2 per lane)
#define BPB  (WPB * BPW)  // 32 b per block
#define JSTR 260          // h row stride (floats): ==4 mod 32 banks, 16B aligned
#define CSTR 8            // h channel stride (floats), tight pack + parity swizzle

// dynamic smem layout (float offsets) — no WT anymore
#define OFF_HS   0                        // WPB*BPW*JSTR = 8320
#define OFF_MC   (OFF_HS + WPB*BPW*JSTR)  // 32*12
#define OFF_MA   (OFF_MC + 384)           // 8*12 (5 used)
#define OFF_NSC  (OFF_MA + 96)
#define OFF_LB   (OFF_NSC + 32)
#define OFF_RW   (OFF_LB + 32)
#define OFF_RB   (OFF_RW + 32)
#define SMEM_FLOATS (OFF_RB + 4)
#define SMEM_BYTES  (SMEM_FLOATS * 4)     // ~35.6KB -> 5 blocks/SM

__global__ __launch_bounds__(128, 5) void dynamics_kernel(
    const float* __restrict__ state,       // [B, 32, 8]
    const int*   __restrict__ action,      // [B]
    const float* __restrict__ act_bv,      // [5, 3]
    const float* __restrict__ norm_scale,  // [32]
    const float* __restrict__ rotor_bv,    // [32, 3]
    const float* __restrict__ lin_b,       // [32]
    const float* __restrict__ reward_W,    // [1, 32]
    const float* __restrict__ reward_b,    // [1]
    float* __restrict__ out,               // [B] reward, then [B,32,8] next_state
    int B)
{
    extern __shared__ __align__(16) float dsm[];
    float* HS  = dsm + OFF_HS;
    float* MC  = dsm + OFF_MC;   // MC[c*12 + 0..8]
    float* MA  = dsm + OFF_MA;   // MA[a*12 + 0..8]
    float* NSC = dsm + OFF_NSC;
    float* LB  = dsm + OFF_LB;
    float* RW  = dsm + OFF_RW;
    float* RB  = dsm + OFF_RB;

    const int tid  = threadIdx.x;
    const int lane = tid & 31;
    const int wid  = tid >> 5;
    const int j    = lane >> 3;   // batch row within warp (pass adds +4)
    const int og   = lane & 7;    // channel octet index
    const int swA  = (og & 4) ? 4 : 0;   // parity swizzle: store half-offsets
    const int swB  = 4 - swA;

    // ---- stage params ----
    if (tid < NCH) {
        NSC[tid] = norm_scale[tid];
        LB[tid]  = lin_b[tid];
        RW[tid]  = reward_W[tid];
        float r[4], m[9];
        rotor_exp4(-0.5f * rotor_bv[tid * 3 + 0],
                   -0.5f * rotor_bv[tid * 3 + 1],
                   -0.5f * rotor_bv[tid * 3 + 2], r);
        rotor_to_mat(r, m);
#pragma unroll
        for (int e = 0; e < 9; e++) MC[tid * 12 + e] = m[e];
    }
    if (tid >= 32 && tid < 37) {
        const int a = tid - 32;
        float r[4], m[9];
        rotor_exp4(-0.5f * act_bv[a * 3 + 0],
                   -0.5f * act_bv[a * 3 + 1],
                   -0.5f * act_bv[a * 3 + 2], r);
        rotor_to_mat(r, m);
#pragma unroll
        for (int e = 0; e < 9; e++) MA[a * 12 + e] = m[e];
    }
    if (tid == 40) RB[0] = reward_b[0];
    __syncthreads();

    float* hw = HS + wid * (BPW * JSTR);
    const int bbase = blockIdx.x * BPB + wid * BPW;

    u64 acc[2][4][4];   // [pass][r][dpair]

    // ---- prework: two passes, 4 b each; lane owns b = bbase + p*4 + j ----
#pragma unroll
    for (int p = 0; p < 2; p++) {
        const int jrow = p * 4 + j;
        int b = bbase + jrow;
        b = (b < B) ? b : (B - 1);

        const int act = action[b];
        const float4 A0 = *(const float4*)&MA[act * 12 + 0];
        const float4 A1 = *(const float4*)&MA[act * 12 + 4];
        const float  A2 = MA[act * 12 + 8];
        const float* sbase = state + (((size_t)b * NCH) << 3);

#pragma unroll
        for (int r = 0; r < 4; r++) {
            const int c = og + 8 * r;
            const float4* sp = (const float4*)(sbase + ((size_t)c << 3));
            const float4 vA = sp[0];
            const float4 vB = sp[1];
            const float s0 = vA.x, s1 = vA.y, s2 = vA.z, s3 = vA.w;
            const float s4 = vB.x, s5 = vB.y, s6 = vB.z, s7 = vB.w;

            // x = R s R~ : scalar/pseudo invariant; vector + dual-bivector rotate
            float xv1, xv2, xv3, xb1, xb2, xb3;
            mat_apply(A0, A1, A2, s1, s2, s4, xv1, xv2, xv3);
            mat_apply(A0, A1, A2, s6, -s5, s3, xb1, xb2, xb3);
            const float x0 = s0, x1 = xv1, x2 = xv2, x3 = xb3,
                        x4 = xv3, x5 = -xb2, x6 = xb1, x7 = s7;

            float nn = 1e-6f;
            nn = fmaf(x0, x0, nn); nn = fmaf(x1, x1, nn);
            nn = fmaf(x2, x2, nn); nn = fmaf(x3, x3, nn);
            nn = fmaf(x4, x4, nn); nn = fmaf(x5, x5, nn);
            nn = fmaf(x6, x6, nn); nn = fmaf(x7, x7, nn);
            const float inv = rsqrtf(nn) * NSC[c];
            const float g0 = x0 * inv;
            const float gate = 0.5f * (1.0f + erff(g0 * 0.70710678118654752f));
            const float sc = inv * gate;
            const float h0 = x0 * sc, h1 = x1 * sc, h2 = x2 * sc, h3 = x3 * sc;
            const float h4 = x4 * sc, h5 = x5 * sc, h6 = x6 * sc, h7 = x7 * sc;

            const float4 C0 = *(const float4*)&MC[c * 12 + 0];
            const float4 C1 = *(const float4*)&MC[c * 12 + 4];
            const float  C2 = MC[c * 12 + 8];
            float yv1, yv2, yv3, yb1, yb2, yb3;
            mat_apply(C0, C1, C2, h1, h2, h4, yv1, yv2, yv3);
            mat_apply(C0, C1, C2, h6, -h5, h3, yb1, yb2, yb3);

            // parity-swizzled store: halves swapped when c&4
            float* hp = hw + jrow * JSTR + c * CSTR;
            *(float4*)(hp + swA) = make_float4(h0, yv1, yv2, yb3);
            *(float4*)(hp + swB) = make_float4(yv3, -yb2, yb1, h7);

            acc[p][r][0] = pack2(x0 + LB[c], x1);
            acc[p][r][1] = pack2(x2, x3);
            acc[p][r][2] = pack2(x4, x5);
            acc[p][r][3] = pack2(x6, x7);
        }
    }
    __syncwarp();

    // ---- grade-tied channel mix ----
    // h from shared (4 LDS.128 per i), W via __ldg broadcast: for fixed (i,r) the
    // 8 og-lanes hit ONE contiguous 128B line of WT_G (L1-resident, dedup'd).
    const float4* Wg4 = (const float4*)WT_G;
#pragma unroll 4
    for (int i = 0; i < NCH; i++) {
        const int rsA = (i & 4) ? 4 : 0;   // compile-time under unroll
        const int rsB = 4 - rsA;
        const float* hp0 = hw + j * JSTR + i * CSTR;         // pass 0 row
        const float* hp1 = hw + (4 + j) * JSTR + i * CSTR;   // pass 1 row
        const ulonglong2 hA0 = *(const ulonglong2*)(hp0 + rsA);
        const ulonglong2 hB0 = *(const ulonglong2*)(hp0 + rsB);
        const ulonglong2 hA1 = *(const ulonglong2*)(hp1 + rsA);
        const ulonglong2 hB1 = *(const ulonglong2*)(hp1 + rsB);
        const float4* wrow = Wg4 + i * 32 + og;
#pragma unroll
        for (int r = 0; r < 4; r++) {
            const float4 w = __ldg(wrow + 8 * r);
            const u64 w01 = pack2(w.x, w.y);
            const u64 w12 = pack2(w.y, w.z);
            const u64 w23 = pack2(w.z, w.w);
            fma2(acc[0][r][0], hA0.x, w01);
            fma2(acc[0][r][1], hA0.y, w12);
            fma2(acc[0][r][2], hB0.x, w12);
            fma2(acc[0][r][3], hB0.y, w23);
            fma2(acc[1][r][0], hA1.x, w01);
            fma2(acc[1][r][1], hA1.y, w12);
            fma2(acc[1][r][2], hB1.x, w12);
            fma2(acc[1][r][3], hB1.y, w23);
        }
    }

    // ---- epilogue: next_state + reward for both passes ----
#pragma unroll
    for (int p = 0; p < 2; p++) {
        const int b = bbase + p * 4 + j;
        const bool valid = (b < B);
        if (valid) {
#pragma unroll
            for (int r = 0; r < 4; r++) {
                const int c = og + 8 * r;
                float* ns = out + B + (((size_t)b * NCH + c) << 3);
                ulonglong2 v0; v0.x = acc[p][r][0]; v0.y = acc[p][r][1];
                ulonglong2 v1; v1.x = acc[p][r][2]; v1.y = acc[p][r][3];
                *(ulonglong2*)(ns + 0) = v0;
                *(ulonglong2*)(ns + 4) = v1;
            }
        }
        float rv = 0.f;
#pragma unroll
        for (int r = 0; r < 4; r++) rv = fmaf(low2(acc[p][r][0]), RW[og + 8 * r], rv);
#pragma unroll
        for (int off = 4; off; off >>= 1) rv += __shfl_xor_sync(0xffffffffu, rv, off);
        if (og == 0 && valid) out[b] = rv + RB[0];
    }
}

extern "C" void kernel_launch(void* const* d_in, const int* in_sizes, int n_in,
                              void* d_out, int out_size) {
    const float* state      = (const float*)d_in[0];
    const int*   action     = (const int*)  d_in[1];
    const float* act_bv     = (const float*)d_in[2];
    const float* norm_scale = (const float*)d_in[3];
    const float* rotor_bv   = (const float*)d_in[4];
    const float* lin_W      = (const float*)d_in[5];
    const float* lin_b      = (const float*)d_in[6];
    const float* reward_W   = (const float*)d_in[7];
    const float* reward_b   = (const float*)d_in[8];
    float* out = (float*)d_out;

    const int B = in_sizes[1];               // action count

    // 1) transpose W into aligned global scratch (graph node, same stream)
    transpose_W_kernel<<<32, 128>>>(lin_W);

    // 2) main kernel
    const int blocks = (B + BPB - 1) / BPB;  // 32 batch rows per block
    cudaFuncSetAttribute(dynamics_kernel,
                         cudaFuncAttributeMaxDynamicSharedMemorySize, SMEM_BYTES);
    dynamics_kernel<<<blocks, 128, SMEM_BYTES>>>(state, action, act_bv, norm_scale,
                                                 rotor_bv, lin_b, reward_W,
                                                 reward_b, out, B);
}

// round 13
// speedup vs baseline: 1.8287x; 1.8287x over previous
#include <cuda_runtime.h>
#include <math.h>

typedef unsigned long long u64;

// ---- packed f32x2 helpers ----
__device__ __forceinline__ u64 pack2(float lo, float hi) {
    u64 r; asm("mov.b64 %0, {%1, %2};" : "=l"(r) : "f"(lo), "f"(hi)); return r;
}
__device__ __forceinline__ float low2(u64 v) {
    float lo, hi; asm("mov.b64 {%0, %1}, %2;" : "=f"(lo), "=f"(hi) : "l"(v)); return lo;
}
__device__ __forceinline__ void fma2(u64& d, u64 a, u64 b) {
    asm("fma.rn.f32x2 %0, %1, %2, %0;" : "+l"(d) : "l"(a), "l"(b));
}

// rotor_exp of bivector -> components {scalar, e12, e13, e23}
__device__ __forceinline__ void rotor_exp4(float b0, float b1, float b2, float r[4]) {
    float t2 = fmaf(b0, b0, fmaf(b1, b1, b2 * b2));
    float th = sqrtf(t2);
    float sn, cs;
    sincosf(th, &sn, &cs);
    float sinc = (th > 1e-6f) ? sn / fmaxf(th, 1e-6f) : 1.0f;
    r[0] = cs; r[1] = sinc * b0; r[2] = sinc * b1; r[3] = sinc * b2;
}

// 3x3 rotation matrix from unit rotor u = (scalar, e12, e13, e23).
__device__ __forceinline__ void rotor_to_mat(const float u[4], float m[9]) {
    const float qw = u[0], qx = -u[3], qy = u[2], qz = -u[1];
    const float x2 = qx + qx, y2 = qy + qy, z2 = qz + qz;
    const float xx = qx * x2, yy = qy * y2, zz = qz * z2;
    const float xy = qx * y2, xz = qx * z2, yz = qy * z2;
    const float wx = qw * x2, wy = qw * y2, wz = qw * z2;
    m[0] = 1.f - (yy + zz); m[1] = xy - wz;        m[2] = xz + wy;
    m[3] = xy + wz;         m[4] = 1.f - (xx + zz); m[5] = yz - wx;
    m[6] = xz - wy;         m[7] = yz + wx;        m[8] = 1.f - (xx + yy);
}

__device__ __forceinline__ void mat_apply(const float4 A0, const float4 A1, const float A2,
                                          float v1, float v2, float v3,
                                          float& o1, float& o2, float& o3) {
    o1 = fmaf(A0.x, v1, fmaf(A0.y, v2, A0.z * v3));
    o2 = fmaf(A0.w, v1, fmaf(A1.x, v2, A1.y * v3));
    o3 = fmaf(A1.z, v1, fmaf(A1.w, v2, A2  * v3));
}

#define NCH  32
#define WPB  4            // warps per block (128 threads)
#define BPW  8            // batch rows per warp (2 per lane)
#define BPB  (WPB * BPW)  // 32 b per block-tile
#define JSTR 260          // h row stride (floats): ==4 mod 32 banks, 16B aligned
#define CSTR 8            // h channel stride (floats), tight pack + parity swizzle
#define GRID 608          // persistent grid: 152 SMs x 4 blocks

// dynamic smem layout (float offsets)
#define OFF_WT   0                        // 4096
#define OFF_HS   4096                     // WPB*BPW*JSTR = 8320
#define OFF_MC   (OFF_HS + WPB*BPW*JSTR)  // 32*12
#define OFF_MA   (OFF_MC + 384)           // 8*12 (5 used)
#define OFF_NSC  (OFF_MA + 96)
#define OFF_LB   (OFF_NSC + 32)
#define OFF_RW   (OFF_LB + 32)
#define OFF_RB   (OFF_RW + 32)
#define SMEM_FLOATS (OFF_RB + 4)
#define SMEM_BYTES  (SMEM_FLOATS * 4)     // ~52KB -> 4 blocks/SM

__global__ __launch_bounds__(128, 4) void dynamics_kernel(
    const float* __restrict__ state,       // [B, 32, 8]
    const int*   __restrict__ action,      // [B]
    const float* __restrict__ act_bv,      // [5, 3]
    const float* __restrict__ norm_scale,  // [32]
    const float* __restrict__ rotor_bv,    // [32, 3]
    const float* __restrict__ lin_W,       // [32, 32, 4]
    const float* __restrict__ lin_b,       // [32]
    const float* __restrict__ reward_W,    // [1, 32]
    const float* __restrict__ reward_b,    // [1]
    float* __restrict__ out,               // [B] reward, then [B,32,8] next_state
    int B, int ntiles)
{
    extern __shared__ __align__(16) float dsm[];
    float* WT  = dsm + OFF_WT;   // WT[i*128 + o*4 + k]
    float* HS  = dsm + OFF_HS;
    float* MC  = dsm + OFF_MC;   // MC[c*12 + 0..8]
    float* MA  = dsm + OFF_MA;   // MA[a*12 + 0..8]
    float* NSC = dsm + OFF_NSC;
    float* LB  = dsm + OFF_LB;
    float* RW  = dsm + OFF_RW;
    float* RB  = dsm + OFF_RB;

    const int tid  = threadIdx.x;
    const int lane = tid & 31;
    const int wid  = tid >> 5;
    const int j    = lane >> 3;   // batch row within warp (pass adds +4)
    const int og   = lane & 7;    // channel octet index
    const int swA  = (og & 4) ? 4 : 0;   // parity swizzle: store half-offsets
    const int swB  = 4 - swA;

    // ---- stage params ONCE per persistent block ----
    for (int s = tid; s < NCH * 128; s += 128) {
        const int o = s >> 7, i = (s >> 2) & 31, k = s & 3;
        WT[i * 128 + o * 4 + k] = lin_W[s];
    }
    if (tid < NCH) {
        NSC[tid] = norm_scale[tid];
        LB[tid]  = lin_b[tid];
        RW[tid]  = reward_W[tid];
        float r[4], m[9];
        rotor_exp4(-0.5f * rotor_bv[tid * 3 + 0],
                   -0.5f * rotor_bv[tid * 3 + 1],
                   -0.5f * rotor_bv[tid * 3 + 2], r);
        rotor_to_mat(r, m);
#pragma unroll
        for (int e = 0; e < 9; e++) MC[tid * 12 + e] = m[e];
    }
    if (tid >= 32 && tid < 37) {
        const int a = tid - 32;
        float r[4], m[9];
        rotor_exp4(-0.5f * act_bv[a * 3 + 0],
                   -0.5f * act_bv[a * 3 + 1],
                   -0.5f * act_bv[a * 3 + 2], r);
        rotor_to_mat(r, m);
#pragma unroll
        for (int e = 0; e < 9; e++) MA[a * 12 + e] = m[e];
    }
    if (tid == 40) RB[0] = reward_b[0];
    __syncthreads();

    float* hw = HS + wid * (BPW * JSTR);

    // ---- persistent tile loop (h tile is warp-private -> __syncwarp only) ----
    for (int tile = blockIdx.x; tile < ntiles; tile += GRID) {
        const int bbase = tile * BPB + wid * BPW;

        u64 acc[2][4][4];   // [pass][r][dpair]

        // ---- prework: two passes, 4 b each; lane owns b = bbase + p*4 + j ----
#pragma unroll
        for (int p = 0; p < 2; p++) {
            const int jrow = p * 4 + j;
            int b = bbase + jrow;
            b = (b < B) ? b : (B - 1);

            const int act = action[b];
            const float4 A0 = *(const float4*)&MA[act * 12 + 0];
            const float4 A1 = *(const float4*)&MA[act * 12 + 4];
            const float  A2 = MA[act * 12 + 8];
            const float* sbase = state + (((size_t)b * NCH) << 3);

#pragma unroll
            for (int r = 0; r < 4; r++) {
                const int c = og + 8 * r;
                const float4* sp = (const float4*)(sbase + ((size_t)c << 3));
                const float4 vA = sp[0];
                const float4 vB = sp[1];
                const float s0 = vA.x, s1 = vA.y, s2 = vA.z, s3 = vA.w;
                const float s4 = vB.x, s5 = vB.y, s6 = vB.z, s7 = vB.w;

                // x = R s R~ : scalar/pseudo invariant; vector + dual-bivector rotate
                float xv1, xv2, xv3, xb1, xb2, xb3;
                mat_apply(A0, A1, A2, s1, s2, s4, xv1, xv2, xv3);
                mat_apply(A0, A1, A2, s6, -s5, s3, xb1, xb2, xb3);
                const float x0 = s0, x1 = xv1, x2 = xv2, x3 = xb3,
                            x4 = xv3, x5 = -xb2, x6 = xb1, x7 = s7;

                float nn = 1e-6f;
                nn = fmaf(x0, x0, nn); nn = fmaf(x1, x1, nn);
                nn = fmaf(x2, x2, nn); nn = fmaf(x3, x3, nn);
                nn = fmaf(x4, x4, nn); nn = fmaf(x5, x5, nn);
                nn = fmaf(x6, x6, nn); nn = fmaf(x7, x7, nn);
                const float inv = rsqrtf(nn) * NSC[c];
                const float g0 = x0 * inv;
                const float gate = 0.5f * (1.0f + erff(g0 * 0.70710678118654752f));
                const float sc = inv * gate;
                const float h0 = x0 * sc, h1 = x1 * sc, h2 = x2 * sc, h3 = x3 * sc;
                const float h4 = x4 * sc, h5 = x5 * sc, h6 = x6 * sc, h7 = x7 * sc;

                const float4 C0 = *(const float4*)&MC[c * 12 + 0];
                const float4 C1 = *(const float4*)&MC[c * 12 + 4];
                const float  C2 = MC[c * 12 + 8];
                float yv1, yv2, yv3, yb1, yb2, yb3;
                mat_apply(C0, C1, C2, h1, h2, h4, yv1, yv2, yv3);
                mat_apply(C0, C1, C2, h6, -h5, h3, yb1, yb2, yb3);

                // parity-swizzled store: halves swapped when c&4
                float* hp = hw + jrow * JSTR + c * CSTR;
                *(float4*)(hp + swA) = make_float4(h0, yv1, yv2, yb3);
                *(float4*)(hp + swB) = make_float4(yv3, -yb2, yb1, h7);

                acc[p][r][0] = pack2(x0 + LB[c], x1);
                acc[p][r][1] = pack2(x2, x3);
                acc[p][r][2] = pack2(x4, x5);
                acc[p][r][3] = pack2(x6, x7);
            }
        }
        __syncwarp();

        // ---- grade-tied channel mix: W loaded once per (i,r), reused for 2 b ----
        // unroll 8 so (i&4) stays compile-time and scheduler gets long windows
#pragma unroll 8
        for (int i = 0; i < NCH; i++) {
            const int rsA = (i & 4) ? 4 : 0;
            const int rsB = 4 - rsA;
            const float* hp0 = hw + j * JSTR + i * CSTR;         // pass 0 row
            const float* hp1 = hw + (4 + j) * JSTR + i * CSTR;   // pass 1 row
            const ulonglong2 hA0 = *(const ulonglong2*)(hp0 + rsA);
            const ulonglong2 hB0 = *(const ulonglong2*)(hp0 + rsB);
            const ulonglong2 hA1 = *(const ulonglong2*)(hp1 + rsA);
            const ulonglong2 hB1 = *(const ulonglong2*)(hp1 + rsB);
#pragma unroll
            for (int r = 0; r < 4; r++) {
                const float4 w = *(const float4*)&WT[i * 128 + (og + 8 * r) * 4];
                const u64 w01 = pack2(w.x, w.y);
                const u64 w12 = pack2(w.y, w.z);
                const u64 w23 = pack2(w.z, w.w);
                fma2(acc[0][r][0], hA0.x, w01);
                fma2(acc[0][r][1], hA0.y, w12);
                fma2(acc[0][r][2], hB0.x, w12);
                fma2(acc[0][r][3], hB0.y, w23);
                fma2(acc[1][r][0], hA1.x, w01);
                fma2(acc[1][r][1], hA1.y, w12);
                fma2(acc[1][r][2], hB1.x, w12);
                fma2(acc[1][r][3], hB1.y, w23);
            }
        }

        // ---- epilogue: next_state + reward for both passes ----
#pragma unroll
        for (int p = 0; p < 2; p++) {
            const int b = bbase + p * 4 + j;
            const bool valid = (b < B);
            if (valid) {
#pragma unroll
                for (int r = 0; r < 4; r++) {
                    const int c = og + 8 * r;
                    float* ns = out + B + (((size_t)b * NCH + c) << 3);
                    ulonglong2 v0; v0.x = acc[p][r][0]; v0.y = acc[p][r][1];
                    ulonglong2 v1; v1.x = acc[p][r][2]; v1.y = acc[p][r][3];
                    *(ulonglong2*)(ns + 0) = v0;
                    *(ulonglong2*)(ns + 4) = v1;
                }
            }
            float rv = 0.f;
#pragma unroll
            for (int r = 0; r < 4; r++) rv = fmaf(low2(acc[p][r][0]), RW[og + 8 * r], rv);
#pragma unroll
            for (int off = 4; off; off >>= 1) rv += __shfl_xor_sync(0xffffffffu, rv, off);
            if (og == 0 && valid) out[b] = rv + RB[0];
        }

        __syncwarp();   // h tile reuse hazard across tile iterations (warp-private)
    }
}

extern "C" void kernel_launch(void* const* d_in, const int* in_sizes, int n_in,
                              void* d_out, int out_size) {
    const float* state      = (const float*)d_in[0];
    const int*   action     = (const int*)  d_in[1];
    const float* act_bv     = (const float*)d_in[2];
    const float* norm_scale = (const float*)d_in[3];
    const float* rotor_bv   = (const float*)d_in[4];
    const float* lin_W      = (const float*)d_in[5];
    const float* lin_b      = (const float*)d_in[6];
    const float* reward_W   = (const float*)d_in[7];
    const float* reward_b   = (const float*)d_in[8];
    float* out = (float*)d_out;

    const int B = in_sizes[1];               // action count
    const int ntiles = (B + BPB - 1) / BPB;  // 32 batch rows per tile
    const int blocks = (ntiles < GRID) ? ntiles : GRID;

    cudaFuncSetAttribute(dynamics_kernel,
                         cudaFuncAttributeMaxDynamicSharedMemorySize, SMEM_BYTES);
    dynamics_kernel<<<blocks, 128, SMEM_BYTES>>>(state, action, act_bv, norm_scale,
                                                 rotor_bv, lin_W, lin_b, reward_W,
                                                 reward_b, out, B, ntiles);
}